// round 16
// baseline (speedup 1.0000x reference)
#include <cuda_runtime.h>
#include <cuda_bf16.h>
#include <cstdint>

#define BB 256
#define TT 100
#define CC 40
#define H1 1024
#define H2 512
#define OO 35
#define TPAD 105            // p1s row stride (105 mod 32 = 9, odd -> conflict-free)

typedef unsigned long long u64;

// ---------------- static device scratch ----------------
__device__ int g_flagT[BB * 8];    // per (b, h-tile): any L1 spike

__device__ __forceinline__ float sigmoidf_(float xr) {
    return (xr >= 0.0f) ? (1.0f / (1.0f + expf(-xr)))
                        : (expf(xr) / (1.0f + expf(xr)));
}
__device__ __forceinline__ uint32_t smem_to_u32(const void* p) {
    uint32_t a;
    asm("{ .reg .u64 t; cvta.to.shared.u64 t, %1; cvt.u32.u64 %0, t; }" : "=r"(a) : "l"(p));
    return a;
}
#define SW128(off) ((off) ^ (((off) >> 3) & 0x70))

#define LDSM_X4(r, addr)                                                              \
    asm volatile("ldmatrix.sync.aligned.m8n8.x4.shared.b16 {%0,%1,%2,%3}, [%4];"      \
        : "=r"((r)[0]), "=r"((r)[1]), "=r"((r)[2]), "=r"((r)[3]) : "r"(addr))
#define LDSM_X2(r, addr)                                                              \
    asm volatile("ldmatrix.sync.aligned.m8n8.x2.shared.b16 {%0,%1}, [%2];"            \
        : "=r"((r)[0]), "=r"((r)[1]) : "r"(addr))
#define MMA16816(d, a, b)                                                             \
    asm volatile("mma.sync.aligned.m16n8k16.row.col.f32.bf16.bf16.f32 "               \
        "{%0,%1,%2,%3}, {%4,%5,%6,%7}, {%8,%9}, {%0,%1,%2,%3};"                       \
        : "+f"((d)[0]), "+f"((d)[1]), "+f"((d)[2]), "+f"((d)[3])                      \
        : "r"((a)[0]), "r"((a)[1]), "r"((a)[2]), "r"((a)[3]),                         \
          "r"((b)[0]), "r"((b)[1]))

// smem layout (bytes)
#define OFF_A    0                        // 112 rows x 128B (SW128) bf16 xd tile
#define OFF_B    14336                    // 128 rows x 128B (SW128) bf16 W tile
#define OFF_P1   30720                    // 128*TPAD floats (also stages raw x: 4000 fl)
#define OFF_SH   (OFF_P1 + 128*TPAD*4)    // 128 floats
#define OFF_OM   (OFF_SH + 512)           // 128 floats
#define OFF_SC   (OFF_OM + 512)           // 128 floats
#define OFF_FLI  (OFF_SC + 512)           // 40 ints
#define OFF_FRAC (OFF_FLI + 160)          // 40 floats
#define OFF_ANY  (OFF_FRAC + 160)         // 1 int
#define SMEM_BYTES (OFF_ANY + 16)

// =======================================================================================
// fused: in-CTA xd build + W pack + HMMA GEMM + in-smem adLIF spike scan.
// blk = b*8 + ht (2048 blocks).
// =======================================================================================
__global__ __launch_bounds__(256) void fused_all_kernel(
    const float* __restrict__ x,
    const float* __restrict__ delay_raw,
    const float* __restrict__ W_delay,
    const float* __restrict__ bn1_gamma, const float* __restrict__ bn1_beta,
    const float* __restrict__ bn1_mean,  const float* __restrict__ bn1_var,
    const float* __restrict__ alpha1, const float* __restrict__ rho1, const float* __restrict__ beta_a1)
{
    extern __shared__ char sm[];
    const int tid = threadIdx.x;

    char*  As    = sm + OFF_A;
    char*  Bs    = sm + OFF_B;
    float* p1s   = (float*)(sm + OFF_P1);     // later: [128][TPAD]; now: x staging
    float* shs   = (float*)(sm + OFF_SH);
    float* oms   = (float*)(sm + OFF_OM);
    float* scs   = (float*)(sm + OFF_SC);
    int*   fli   = (int*)(sm + OFF_FLI);
    float* frac  = (float*)(sm + OFF_FRAC);
    int*   s_any = (int*)(sm + OFF_ANY);

    const int blk = blockIdx.x;
    const int ht  = blk & 7;
    const int b   = blk >> 3;
    const int h0  = ht * 128;

    // ---- phase 0: constants + stage raw x[b] into p1s region ----
    if (tid < CC) {
        float d  = sigmoidf_(delay_raw[tid]) * 30.0f;    // MAX_DELAY
        float fl = floorf(d);
        fli[tid]  = (int)fl;
        frac[tid] = d - fl;
    }
    if (tid < 128) {
        int h = h0 + tid;
        float sc = bn1_gamma[h] * rsqrtf(bn1_var[h] + 1e-5f);
        scs[tid] = sc;
        shs[tid] = bn1_beta[h] - bn1_mean[h] * sc;
        oms[tid] = 1.0f - alpha1[h];
    }
    if (tid == 0) *s_any = 0;
    {
        const float* xb = x + (size_t)b * TT * CC;
        for (int i = tid; i < TT * CC; i += 256) p1s[i] = xb[i];
    }
    __syncthreads();

    // ---- phase 1: build As (interpolated xd, bf16, SW128) + Bs (W*sc, bf16, SW128) ----
    for (int i = tid; i < 112 * 32; i += 256) {        // t-rows 0..111 (>=100 zero)
        int t = i >> 5, pc = i & 31;
        float v0 = 0.f, v1 = 0.f;
        if (t < TT) {
            int c0 = 2 * pc, c1 = 2 * pc + 1;
            if (c0 < CC) {
                int i0 = t - fli[c0]; float fr = frac[c0];
                float a0 = (i0 >= 0) ? p1s[i0 * CC + c0]       : 0.0f;
                float a1 = (i0 >= 1) ? p1s[(i0 - 1) * CC + c0] : 0.0f;
                v0 = (1.0f - fr) * a0 + fr * a1;
            }
            if (c1 < CC) {
                int i0 = t - fli[c1]; float fr = frac[c1];
                float a0 = (i0 >= 0) ? p1s[i0 * CC + c1]       : 0.0f;
                float a1 = (i0 >= 1) ? p1s[(i0 - 1) * CC + c1] : 0.0f;
                v1 = (1.0f - fr) * a0 + fr * a1;
            }
        }
        __nv_bfloat162 bb = __float22bfloat162_rn(make_float2(v0, v1));
        *(uint32_t*)(As + SW128((uint32_t)(t * 128 + pc * 4))) = *(uint32_t*)&bb;
    }
    for (int i = tid; i < 128 * 32; i += 256) {
        int hl = i >> 5, pc = i & 31;
        int c0 = 2 * pc, c1 = 2 * pc + 1;
        const float* wrow = W_delay + (size_t)(h0 + hl) * CC;
        float sc = scs[hl];
        float w0 = (c0 < CC) ? wrow[c0] * sc : 0.0f;
        float w1 = (c1 < CC) ? wrow[c1] * sc : 0.0f;
        __nv_bfloat162 bb = __float22bfloat162_rn(make_float2(w0, w1));
        *(uint32_t*)(Bs + SW128((uint32_t)(hl * 128 + pc * 4))) = *(uint32_t*)&bb;
    }
    __syncthreads();

    // ---- phase 2: MMA 7 m-tiles (112 rows) x warp n-strip (16 cols) x 4 k-steps ----
    const int wid  = tid >> 5;
    const int lane = tid & 31;
    const int nbase = wid * 16;

    const uint32_t a_base = smem_to_u32(As);
    const uint32_t b_base = smem_to_u32(Bs);
    const uint32_t a_row  = lane & 15;
    const uint32_t a_bco  = (lane >> 4) * 16;
    const uint32_t b_row  = lane & 7;
    const uint32_t b_bco  = ((lane >> 3) & 1) * 16;

    float d[7][2][4];
    #pragma unroll
    for (int mt = 0; mt < 7; mt++)
        #pragma unroll
        for (int nt = 0; nt < 2; nt++)
            #pragma unroll
            for (int j = 0; j < 4; j++) d[mt][nt][j] = 0.0f;

    #pragma unroll
    for (int kt = 0; kt < 4; kt++) {
        uint32_t a[7][4];
        #pragma unroll
        for (int mt = 0; mt < 7; mt++) {
            uint32_t off = (mt * 16 + a_row) * 128 + kt * 32 + a_bco;
            LDSM_X4(a[mt], a_base + SW128(off));
        }
        #pragma unroll
        for (int nt = 0; nt < 2; nt++) {
            uint32_t off = (nbase + nt * 8 + b_row) * 128 + kt * 32 + b_bco;
            uint32_t bfr[2];
            LDSM_X2(bfr, b_base + SW128(off));
            #pragma unroll
            for (int mt = 0; mt < 7; mt++)
                MMA16816(d[mt][nt], a[mt], bfr);
        }
    }

    // ---- phase 3: epilogue (acc + shift)*(1-alpha) -> p1s[col][t] (overwrites staging)
    const int tr = lane >> 2;
    const int tc = (lane & 3) * 2;
    #pragma unroll
    for (int mt = 0; mt < 7; mt++) {
        #pragma unroll
        for (int nt = 0; nt < 2; nt++) {
            int col = nbase + nt * 8 + tc;
            float s0 = shs[col], s1 = shs[col + 1];
            float o0 = oms[col], o1 = oms[col + 1];
            #pragma unroll
            for (int half = 0; half < 2; half++) {
                int t = mt * 16 + tr + half * 8;
                if (t < TT) {
                    p1s[col       * TPAD + t] = (d[mt][nt][half * 2 + 0] + s0) * o0;
                    p1s[(col + 1) * TPAD + t] = (d[mt][nt][half * 2 + 1] + s1) * o1;
                }
            }
        }
    }
    __syncthreads();

    // ---- phase 4: barrier-free adLIF spike scan (128 threads, 1 neuron each) ----
    if (tid < 128) {
        int h = h0 + tid;
        const float al = alpha1[h], rh = rho1[h], ba = beta_a1[h];
        float v = 0.f, a = 0.f, s = 0.f;
        int spiked = 0;
        const float* pr = p1s + tid * TPAD;
        #pragma unroll 4
        for (int t = 0; t < TT; t++) {
            float I  = pr[t];
            float an = rh * a + ba * s;
            float vn = al * v + I - an - s;      // THRESH = 1
            s = (vn >= 1.0f) ? 1.0f : 0.0f;
            spiked |= (s != 0.0f);
            a = an; v = vn;
        }
        if (spiked) atomicOr(s_any, 1);
    }
    __syncthreads();
    if (tid == 0) g_flagT[blk] = *s_any;
}

// =======================================================================================
// finalize (R15-proven): quiet -> constant-drive L2 pre-check; silent -> zeros (exact).
//                        any L1 flag or quiet-L2 spike -> full exact re-sim.
// =======================================================================================
__global__ __launch_bounds__(512, 1) void finalize_kernel(
    const float* __restrict__ x,
    const float* __restrict__ delay_raw,
    const float* __restrict__ W_delay,
    const float* __restrict__ bn1_gamma, const float* __restrict__ bn1_beta,
    const float* __restrict__ bn1_mean,  const float* __restrict__ bn1_var,
    const float* __restrict__ alpha1, const float* __restrict__ rho1, const float* __restrict__ beta_a1,
    const float* __restrict__ bn2_gamma, const float* __restrict__ bn2_beta,
    const float* __restrict__ bn2_mean,  const float* __restrict__ bn2_var,
    const float* __restrict__ alpha2, const float* __restrict__ rho2, const float* __restrict__ beta_a2,
    const float* __restrict__ W_rec1, const float* __restrict__ W2,
    const float* __restrict__ W_rec2, const float* __restrict__ W_out,
    const float* __restrict__ beta_out,
    float* __restrict__ out)
{
    const int tid = threadIdx.x;
    const int b   = blockIdx.x;

    __shared__ int flg;
    if (tid == 0) {
        int f = 0;
        #pragma unroll
        for (int k = 0; k < 8; k++) f |= g_flagT[b * 8 + k];
        flg = f;
    }
    __syncthreads();

    if (flg == 0) {
        const float sc2q = bn2_gamma[tid] * rsqrtf(bn2_var[tid] + 1e-5f);
        const float al2q = alpha2[tid];
        const float sh2q = (1.0f - al2q) * (bn2_beta[tid] - bn2_mean[tid] * sc2q);
        float vq = 0.f;
        int spk = 0;
        #pragma unroll 4
        for (int t = 0; t < TT; t++) {
            vq = al2q * vq + sh2q;
            spk |= (vq >= 1.0f);
        }
        int anyq = __syncthreads_or(spk);
        if (!anyq) {
            if (tid < OO) out[b * OO + tid] = 0.0f;   // exact: readout identically zero
            return;
        }
    }

    // ------------------ full correct simulation of batch b -----------------------------
    __shared__ float xd[TT][CC];
    __shared__ int   fli[CC];
    __shared__ float frac[CC];
    __shared__ int l1[2][H1], l2[2][H2];
    __shared__ int c1[2], c2[2];

    if (tid < CC) {
        float d  = sigmoidf_(delay_raw[tid]) * 30.0f;
        float fl = floorf(d);
        fli[tid]  = (int)fl;
        frac[tid] = d - fl;
    }
    if (tid < 2) { c1[tid] = 0; c2[tid] = 0; }
    __syncthreads();

    {
        const float* xb = x + (size_t)b * TT * CC;
        for (int i = tid; i < TT * CC; i += 512) {
            int t = i / CC, c = i - t * CC;
            int i0 = t - fli[c];
            float fr = frac[c];
            float x0 = (i0 >= 0) ? xb[i0 * CC + c]       : 0.0f;
            float x1 = (i0 >= 1) ? xb[(i0 - 1) * CC + c] : 0.0f;
            xd[t][c] = (1.0f - fr) * x0 + fr * x1;
        }
    }

    const int h0 = tid, h1 = tid + 512;
    const float sc10 = bn1_gamma[h0] * rsqrtf(bn1_var[h0] + 1e-5f);
    const float sc11 = bn1_gamma[h1] * rsqrtf(bn1_var[h1] + 1e-5f);
    const float al10 = alpha1[h0], al11 = alpha1[h1];
    const float om10 = 1.0f - al10, om11 = 1.0f - al11;
    const float shc0 = om10 * (bn1_beta[h0] - bn1_mean[h0] * sc10);
    const float shc1 = om11 * (bn1_beta[h1] - bn1_mean[h1] * sc11);
    const float sf0 = sc10 * om10, sf1 = sc11 * om11;
    const float rh10 = rho1[h0], rh11 = rho1[h1];
    const float ba10 = beta_a1[h0], ba11 = beta_a1[h1];
    float Wd0[CC], Wd1[CC];
    #pragma unroll
    for (int c = 0; c < CC; c++) { Wd0[c] = W_delay[h0 * CC + c]; Wd1[c] = W_delay[h1 * CC + c]; }
    float v10 = 0.f, a10 = 0.f, s10 = 0.f;
    float v11 = 0.f, a11 = 0.f, s11 = 0.f;

    const float sc2 = bn2_gamma[tid] * rsqrtf(bn2_var[tid] + 1e-5f);
    const float al2 = alpha2[tid];
    const float om2 = 1.0f - al2;
    const float sh2 = om2 * (bn2_beta[tid] - bn2_mean[tid] * sc2);
    const float scom = sc2 * om2;
    const float rh2 = rho2[tid], ba2 = beta_a2[tid];
    float v2 = 0.f, a2 = 0.f, s2 = 0.f;

    float vo = 0.f, acc = 0.f, bo = 0.f, obo = 0.f;
    if (tid < OO) { bo = beta_out[tid]; obo = 1.0f - bo; }

    __syncthreads();

    for (int t = 0; t < TT; t++) {
        const int q = t & 1, p = q ^ 1;

        float d0 = 0.f, d1 = 0.f;
        #pragma unroll
        for (int c = 0; c < CC; c++) { float xv = xd[t][c]; d0 += Wd0[c] * xv; d1 += Wd1[c] * xv; }
        float r0 = 0.f, r1 = 0.f;
        {
            int n = c1[p];
            for (int j = 0; j < n; j++) {
                int jj = l1[p][j];
                r0 += W_rec1[(size_t)h0 * H1 + jj];
                r1 += W_rec1[(size_t)h1 * H1 + jj];
            }
        }
        {
            float I  = sf0 * (d0 + r0) + shc0;
            float an = rh10 * a10 + ba10 * s10;
            float vn = al10 * v10 + I - an - s10;
            float sn = (vn >= 1.0f) ? 1.0f : 0.0f;
            a10 = an; v10 = vn; s10 = sn;
            if (sn != 0.0f) { int pos = atomicAdd(&c1[q], 1); l1[q][pos] = h0; }
        }
        {
            float I  = sf1 * (d1 + r1) + shc1;
            float an = rh11 * a11 + ba11 * s11;
            float vn = al11 * v11 + I - an - s11;
            float sn = (vn >= 1.0f) ? 1.0f : 0.0f;
            a11 = an; v11 = vn; s11 = sn;
            if (sn != 0.0f) { int pos = atomicAdd(&c1[q], 1); l1[q][pos] = h1; }
        }
        __syncthreads();

        {
            float su = 0.f;
            int m = c1[q];
            for (int j = 0; j < m; j++) su += W2[(size_t)tid * H1 + l1[q][j]];
            int m2 = c2[p];
            for (int j = 0; j < m2; j++) su += W_rec2[(size_t)tid * H2 + l2[p][j]];
            float u  = sh2 + scom * su;
            float an = rh2 * a2 + ba2 * s2;
            float vn = al2 * v2 + u - an - s2;
            float sn = (vn >= 1.0f) ? 1.0f : 0.0f;
            a2 = an; v2 = vn; s2 = sn;
            if (sn != 0.0f) { int pos = atomicAdd(&c2[q], 1); l2[q][pos] = tid; }
        }
        __syncthreads();

        if (tid < OO) {
            float io = 0.f;
            int m = c2[q];
            for (int j = 0; j < m; j++) io += W_out[(size_t)tid * H2 + l2[q][j]];
            vo = bo * vo + obo * io;
            acc += vo;
        }
        if (tid == 0) { c1[p] = 0; c2[p] = 0; }
        __syncthreads();
    }

    if (tid < OO) out[b * OO + tid] = acc * (1.0f / (float)TT);
}

// ---------------- launch ----------------
extern "C" void kernel_launch(void* const* d_in, const int* in_sizes, int n_in,
                              void* d_out, int out_size)
{
    const float* x         = (const float*)d_in[0];
    const float* W_delay   = (const float*)d_in[1];
    const float* delay_raw = (const float*)d_in[2];
    const float* W_rec1    = (const float*)d_in[3];
    const float* W2        = (const float*)d_in[4];
    const float* W_rec2    = (const float*)d_in[5];
    const float* W_out     = (const float*)d_in[6];
    const float* bn1_gamma = (const float*)d_in[7];
    const float* bn1_beta  = (const float*)d_in[8];
    const float* bn1_mean  = (const float*)d_in[9];
    const float* bn1_var   = (const float*)d_in[10];
    const float* bn2_gamma = (const float*)d_in[11];
    const float* bn2_beta  = (const float*)d_in[12];
    const float* bn2_mean  = (const float*)d_in[13];
    const float* bn2_var   = (const float*)d_in[14];
    const float* alpha1    = (const float*)d_in[15];
    const float* rho1      = (const float*)d_in[16];
    const float* beta_a1   = (const float*)d_in[17];
    const float* alpha2    = (const float*)d_in[18];
    const float* rho2      = (const float*)d_in[19];
    const float* beta_a2   = (const float*)d_in[20];
    const float* beta_out  = (const float*)d_in[21];

    static int s_attr_done = 0;
    if (!s_attr_done) {
        cudaFuncSetAttribute(fused_all_kernel,
                             cudaFuncAttributeMaxDynamicSharedMemorySize, SMEM_BYTES);
        s_attr_done = 1;
    }

    fused_all_kernel<<<BB * 8, 256, SMEM_BYTES>>>(
        x, delay_raw, W_delay,
        bn1_gamma, bn1_beta, bn1_mean, bn1_var,
        alpha1, rho1, beta_a1);

    finalize_kernel<<<BB, 512>>>(x, delay_raw, W_delay,
                                 bn1_gamma, bn1_beta, bn1_mean, bn1_var,
                                 alpha1, rho1, beta_a1,
                                 bn2_gamma, bn2_beta, bn2_mean, bn2_var,
                                 alpha2, rho2, beta_a2,
                                 W_rec1, W2, W_rec2, W_out, beta_out,
                                 (float*)d_out);
}

// round 17
// speedup vs baseline: 1.8203x; 1.8203x over previous
#include <cuda_runtime.h>
#include <cuda_bf16.h>
#include <cstdint>

#define BB 256
#define TT 100
#define CC 40
#define H1 1024
#define H2 512
#define OO 35
#define MT (BB*TT)
#define KP 64               // K padded to 64 (c in [40,64) zero)
#define TPADB 102           // bf16 p1s row stride (51 words, odd -> conflict-free)
#define TCHUNK 25           // t-rows per prep block

typedef unsigned long long u64;

// ---------------- static device scratch ----------------
__device__ uint32_t g_xdh[(size_t)MT * (KP/2)];   // delayed input bf16x2, [r][cpair], zero-padded
__device__ uint32_t g_Wdh[H1 * (KP/2)];           // (W_delay*sc1) bf16x2, [h][cpair], zero-padded
__device__ float g_sh1[H1];                       // BN shift
__device__ float g_om1[H1];                       // 1 - alpha1
__device__ int   g_flagT[BB * 8];                 // per (b, h-tile): any L1 spike
__device__ int   g_done[BB];                      // completion counters (zeroed by prep)
__device__ int   g_need[BB];                      // 1 -> finalize must re-sim batch

__device__ __forceinline__ float sigmoidf_(float xr) {
    return (xr >= 0.0f) ? (1.0f / (1.0f + expf(-xr)))
                        : (expf(xr) / (1.0f + expf(xr)));
}
__device__ __forceinline__ uint32_t smem_to_u32(const void* p) {
    uint32_t a;
    asm("{ .reg .u64 t; cvta.to.shared.u64 t, %1; cvt.u32.u64 %0, t; }" : "=r"(a) : "l"(p));
    return a;
}
#define SW128(off) ((off) ^ (((off) >> 3) & 0x70))

#define LDSM_X4(r, addr)                                                              \
    asm volatile("ldmatrix.sync.aligned.m8n8.x4.shared.b16 {%0,%1,%2,%3}, [%4];"      \
        : "=r"((r)[0]), "=r"((r)[1]), "=r"((r)[2]), "=r"((r)[3]) : "r"(addr))
#define LDSM_X2(r, addr)                                                              \
    asm volatile("ldmatrix.sync.aligned.m8n8.x2.shared.b16 {%0,%1}, [%2];"            \
        : "=r"((r)[0]), "=r"((r)[1]) : "r"(addr))
#define MMA16816(d, a, b)                                                             \
    asm volatile("mma.sync.aligned.m16n8k16.row.col.f32.bf16.bf16.f32 "               \
        "{%0,%1,%2,%3}, {%4,%5,%6,%7}, {%8,%9}, {%0,%1,%2,%3};"                       \
        : "+f"((d)[0]), "+f"((d)[1]), "+f"((d)[2]), "+f"((d)[3])                      \
        : "r"((a)[0]), "r"((a)[1]), "r"((a)[2]), "r"((a)[3]),                         \
          "r"((b)[0]), "r"((b)[1]))

// smem layout of fused kernel (bytes)
#define OFF_A    0                          // 112 rows x 128B (SW128)
#define OFF_B    14336                      // 128 rows x 128B (SW128)
#define OFF_P1   30720                      // 128 * TPADB bf16
#define OFF_SH   (OFF_P1 + 128*TPADB*2)     // 128 floats
#define OFF_OM   (OFF_SH + 512)             // 128 floats
#define OFF_ANY  (OFF_OM + 512)             // 1 int
#define SMEM_BYTES (OFF_ANY + 16)           // ~58 KB -> 3 CTAs/SM

// =======================================================================================
// prep+xd (R15-proven): blocks 0..1023 = (batch, t-chunk) gather; 1024..1031 = weights.
// Also zeroes g_done/g_need.
// =======================================================================================
__global__ __launch_bounds__(256) void prep_xd_kernel(
    const float* __restrict__ x,
    const float* __restrict__ delay_raw,
    const float* __restrict__ W_delay,
    const float* __restrict__ g1, const float* __restrict__ b1,
    const float* __restrict__ m1, const float* __restrict__ v1,
    const float* __restrict__ alpha1)
{
    const int tid = threadIdx.x;
    const int blk = blockIdx.x;

    if (blk >= BB * 4) {
        __shared__ float scs[128];
        const int ht = blk - BB * 4;
        if (ht == 0 && tid < BB) { g_done[tid] = 0; g_need[tid] = 0; }
        if (tid < 128) {
            int h = ht * 128 + tid;
            float sc = g1[h] * rsqrtf(v1[h] + 1e-5f);
            scs[tid] = sc;
            g_sh1[h] = b1[h] - m1[h] * sc;
            g_om1[h] = 1.0f - alpha1[h];
        }
        __syncthreads();
        for (int i = tid; i < 128 * (KP/2); i += 256) {
            int hl = i >> 5, pc = i & 31;
            int h = ht * 128 + hl;
            int c0 = 2 * pc, c1 = 2 * pc + 1;
            float w0 = (c0 < CC) ? W_delay[h * CC + c0] * scs[hl] : 0.0f;
            float w1 = (c1 < CC) ? W_delay[h * CC + c1] * scs[hl] : 0.0f;
            __nv_bfloat162 bb = __float22bfloat162_rn(make_float2(w0, w1));
            g_Wdh[(size_t)h * (KP/2) + pc] = *(uint32_t*)&bb;
        }
        return;
    }

    __shared__ float sx[56 * CC];
    __shared__ int   fli[CC];
    __shared__ float frac[CC];

    const int b     = blk >> 2;
    const int chunk = blk & 3;
    const int t0    = chunk * TCHUNK;
    const int lo    = (t0 >= 31) ? (t0 - 31) : 0;
    const int nrows = t0 + TCHUNK - lo;

    if (tid < CC) {
        float d  = sigmoidf_(delay_raw[tid]) * 30.0f;    // MAX_DELAY
        float fl = floorf(d);
        fli[tid]  = (int)fl;
        frac[tid] = d - fl;
    }
    const float* xb = x + (size_t)b * TT * CC;
    for (int i = tid; i < nrows * CC; i += 256) sx[i] = xb[lo * CC + i];
    __syncthreads();

    for (int i = tid; i < TCHUNK * (KP/2); i += 256) {
        int t = t0 + (i >> 5), pc = i & 31;
        float v0 = 0.f, v1v = 0.f;
        int c0 = 2 * pc, c1 = 2 * pc + 1;
        if (c0 < CC) {
            int i0 = t - fli[c0]; float fr = frac[c0];
            float a0 = (i0 >= 0) ? sx[(i0 - lo) * CC + c0]     : 0.0f;
            float a1 = (i0 >= 1) ? sx[(i0 - 1 - lo) * CC + c0] : 0.0f;
            v0 = (1.0f - fr) * a0 + fr * a1;
        }
        if (c1 < CC) {
            int i0 = t - fli[c1]; float fr = frac[c1];
            float a0 = (i0 >= 0) ? sx[(i0 - lo) * CC + c1]     : 0.0f;
            float a1 = (i0 >= 1) ? sx[(i0 - 1 - lo) * CC + c1] : 0.0f;
            v1v = (1.0f - fr) * a0 + fr * a1;
        }
        __nv_bfloat162 bb = __float22bfloat162_rn(make_float2(v0, v1v));
        g_xdh[(size_t)(b * TT + t) * (KP/2) + pc] = *(uint32_t*)&bb;
    }
}

// =======================================================================================
// fused HMMA GEMM + in-smem adLIF spike scan + last-CTA-per-batch quiet resolution.
// blk = b*8 + ht (2048 blocks).
// =======================================================================================
__global__ __launch_bounds__(256) void fused_mma_scan_kernel(
    const float* __restrict__ alpha1, const float* __restrict__ rho1, const float* __restrict__ beta_a1,
    const float* __restrict__ bn2_gamma, const float* __restrict__ bn2_beta,
    const float* __restrict__ bn2_mean,  const float* __restrict__ bn2_var,
    const float* __restrict__ alpha2,
    float* __restrict__ out)
{
    extern __shared__ char sm[];
    const int tid = threadIdx.x;

    char*          As   = sm + OFF_A;
    char*          Bs   = sm + OFF_B;
    __nv_bfloat16* p1s  = (__nv_bfloat16*)(sm + OFF_P1);   // [128][TPADB]
    float*         shs  = (float*)(sm + OFF_SH);
    float*         oms  = (float*)(sm + OFF_OM);
    int*           s_any = (int*)(sm + OFF_ANY);

    const int blk = blockIdx.x;
    const int ht  = blk & 7;
    const int b   = blk >> 3;
    const int h0  = ht * 128;

    // load A: rows t=0..99 real, 100..111 zero-padded; B: W tile
    {
        const uint4* gA = (const uint4*)g_xdh + (size_t)b * TT * 8;
        #pragma unroll
        for (int i = tid; i < 112 * 8; i += 256) {
            int row = i >> 3;
            uint4 v = make_uint4(0u, 0u, 0u, 0u);
            if (row < TT) v = gA[i];
            *(uint4*)(As + SW128((uint32_t)(i * 16))) = v;
        }
        const uint4* gB = (const uint4*)g_Wdh + (size_t)h0 * 8;
        #pragma unroll
        for (int i = tid; i < 1024; i += 256)
            *(uint4*)(Bs + SW128((uint32_t)(i * 16))) = gB[i];
    }
    if (tid < 128) {
        shs[tid] = g_sh1[h0 + tid];
        oms[tid] = g_om1[h0 + tid];
    }
    if (tid == 0) *s_any = 0;
    __syncthreads();

    // MMA: 7 m-tiles (112 rows) x warp n-strip (16 cols) x 4 k-steps
    const int wid  = tid >> 5;
    const int lane = tid & 31;
    const int nbase = wid * 16;

    const uint32_t a_base = smem_to_u32(As);
    const uint32_t b_base = smem_to_u32(Bs);
    const uint32_t a_row  = lane & 15;
    const uint32_t a_bco  = (lane >> 4) * 16;
    const uint32_t b_row  = lane & 7;
    const uint32_t b_bco  = ((lane >> 3) & 1) * 16;

    float d[7][2][4];
    #pragma unroll
    for (int mt = 0; mt < 7; mt++)
        #pragma unroll
        for (int nt = 0; nt < 2; nt++)
            #pragma unroll
            for (int j = 0; j < 4; j++) d[mt][nt][j] = 0.0f;

    #pragma unroll
    for (int kt = 0; kt < 4; kt++) {
        uint32_t a[7][4];
        #pragma unroll
        for (int mt = 0; mt < 7; mt++) {
            uint32_t off = (mt * 16 + a_row) * 128 + kt * 32 + a_bco;
            LDSM_X4(a[mt], a_base + SW128(off));
        }
        #pragma unroll
        for (int nt = 0; nt < 2; nt++) {
            uint32_t off = (nbase + nt * 8 + b_row) * 128 + kt * 32 + b_bco;
            uint32_t bfr[2];
            LDSM_X2(bfr, b_base + SW128(off));
            #pragma unroll
            for (int mt = 0; mt < 7; mt++)
                MMA16816(d[mt][nt], a[mt], bfr);
        }
    }

    // epilogue: (acc + shift)*(1-alpha) -> p1s[col][t] (bf16)
    const int tr = lane >> 2;
    const int tc = (lane & 3) * 2;
    #pragma unroll
    for (int mt = 0; mt < 7; mt++) {
        #pragma unroll
        for (int nt = 0; nt < 2; nt++) {
            int col = nbase + nt * 8 + tc;
            float s0 = shs[col], s1 = shs[col + 1];
            float o0 = oms[col], o1 = oms[col + 1];
            #pragma unroll
            for (int half = 0; half < 2; half++) {
                int t = mt * 16 + tr + half * 8;
                if (t < TT) {
                    p1s[col       * TPADB + t] = __float2bfloat16_rn((d[mt][nt][half * 2 + 0] + s0) * o0);
                    p1s[(col + 1) * TPADB + t] = __float2bfloat16_rn((d[mt][nt][half * 2 + 1] + s1) * o1);
                }
            }
        }
    }
    __syncthreads();

    // barrier-free adLIF spike scan from smem (128 threads, 1 neuron each)
    if (tid < 128) {
        int h = h0 + tid;
        const float al = alpha1[h], rh = rho1[h], ba = beta_a1[h];
        float v = 0.f, a = 0.f, s = 0.f;
        int spiked = 0;
        const __nv_bfloat16* pr = p1s + tid * TPADB;
        #pragma unroll 4
        for (int t = 0; t < TT; t++) {
            float I  = __bfloat162float(pr[t]);
            float an = rh * a + ba * s;
            float vn = al * v + I - an - s;      // THRESH = 1
            s = (vn >= 1.0f) ? 1.0f : 0.0f;
            spiked |= (s != 0.0f);
            a = an; v = vn;
        }
        if (spiked) atomicOr(s_any, 1);
    }
    __syncthreads();

    // last CTA of batch b resolves the quiet case inline
    __shared__ int s_last;
    if (tid == 0) {
        g_flagT[blk] = *s_any;
        __threadfence();
        int prev = atomicAdd(&g_done[b], 1);
        s_last = (prev == 7);
    }
    __syncthreads();
    if (!s_last) return;

    __shared__ int s_f;
    if (tid == 0) {
        int f = 0;
        #pragma unroll
        for (int k = 0; k < 8; k++) f |= g_flagT[b * 8 + k];
        s_f = f;
    }
    __syncthreads();

    if (s_f) {
        if (tid == 0) g_need[b] = 1;
        return;
    }
    // quiet: constant-drive L2 pre-check (exact until first L2 spike); 2 neurons/thread
    int spk = 0;
    {
        const int n0 = tid, n1 = tid + 256;
        const float sca = bn2_gamma[n0] * rsqrtf(bn2_var[n0] + 1e-5f);
        const float ala = alpha2[n0];
        const float sha = (1.0f - ala) * (bn2_beta[n0] - bn2_mean[n0] * sca);
        const float scb = bn2_gamma[n1] * rsqrtf(bn2_var[n1] + 1e-5f);
        const float alb = alpha2[n1];
        const float shb = (1.0f - alb) * (bn2_beta[n1] - bn2_mean[n1] * scb);
        float va = 0.f, vb = 0.f;
        #pragma unroll 4
        for (int t = 0; t < TT; t++) {
            va = ala * va + sha;
            vb = alb * vb + shb;
            spk |= (va >= 1.0f) | (vb >= 1.0f);
        }
    }
    int anyq = __syncthreads_or(spk);
    if (anyq) {
        if (tid == 0) g_need[b] = 1;
    } else {
        if (tid < OO) out[b * OO + tid] = 0.0f;   // exact: readout identically zero
    }
}

// =======================================================================================
// finalize: early-exit unless g_need[b]; else full exact re-sim (R10-proven).
// =======================================================================================
__global__ __launch_bounds__(512, 1) void finalize_kernel(
    const float* __restrict__ x,
    const float* __restrict__ delay_raw,
    const float* __restrict__ W_delay,
    const float* __restrict__ bn1_gamma, const float* __restrict__ bn1_beta,
    const float* __restrict__ bn1_mean,  const float* __restrict__ bn1_var,
    const float* __restrict__ alpha1, const float* __restrict__ rho1, const float* __restrict__ beta_a1,
    const float* __restrict__ bn2_gamma, const float* __restrict__ bn2_beta,
    const float* __restrict__ bn2_mean,  const float* __restrict__ bn2_var,
    const float* __restrict__ alpha2, const float* __restrict__ rho2, const float* __restrict__ beta_a2,
    const float* __restrict__ W_rec1, const float* __restrict__ W2,
    const float* __restrict__ W_rec2, const float* __restrict__ W_out,
    const float* __restrict__ beta_out,
    float* __restrict__ out)
{
    const int tid = threadIdx.x;
    const int b   = blockIdx.x;

    if (g_need[b] == 0) return;     // quiet output already written by fused kernel

    __shared__ float xd[TT][CC];
    __shared__ int   fli[CC];
    __shared__ float frac[CC];
    __shared__ int l1[2][H1], l2[2][H2];
    __shared__ int c1[2], c2[2];

    if (tid < CC) {
        float d  = sigmoidf_(delay_raw[tid]) * 30.0f;
        float fl = floorf(d);
        fli[tid]  = (int)fl;
        frac[tid] = d - fl;
    }
    if (tid < 2) { c1[tid] = 0; c2[tid] = 0; }
    __syncthreads();

    {
        const float* xb = x + (size_t)b * TT * CC;
        for (int i = tid; i < TT * CC; i += 512) {
            int t = i / CC, c = i - t * CC;
            int i0 = t - fli[c];
            float fr = frac[c];
            float x0 = (i0 >= 0) ? xb[i0 * CC + c]       : 0.0f;
            float x1 = (i0 >= 1) ? xb[(i0 - 1) * CC + c] : 0.0f;
            xd[t][c] = (1.0f - fr) * x0 + fr * x1;
        }
    }

    const int h0 = tid, h1 = tid + 512;
    const float sc10 = bn1_gamma[h0] * rsqrtf(bn1_var[h0] + 1e-5f);
    const float sc11 = bn1_gamma[h1] * rsqrtf(bn1_var[h1] + 1e-5f);
    const float al10 = alpha1[h0], al11 = alpha1[h1];
    const float om10 = 1.0f - al10, om11 = 1.0f - al11;
    const float shc0 = om10 * (bn1_beta[h0] - bn1_mean[h0] * sc10);
    const float shc1 = om11 * (bn1_beta[h1] - bn1_mean[h1] * sc11);
    const float sf0 = sc10 * om10, sf1 = sc11 * om11;
    const float rh10 = rho1[h0], rh11 = rho1[h1];
    const float ba10 = beta_a1[h0], ba11 = beta_a1[h1];
    float Wd0[CC], Wd1[CC];
    #pragma unroll
    for (int c = 0; c < CC; c++) { Wd0[c] = W_delay[h0 * CC + c]; Wd1[c] = W_delay[h1 * CC + c]; }
    float v10 = 0.f, a10 = 0.f, s10 = 0.f;
    float v11 = 0.f, a11 = 0.f, s11 = 0.f;

    const float sc2 = bn2_gamma[tid] * rsqrtf(bn2_var[tid] + 1e-5f);
    const float al2 = alpha2[tid];
    const float om2 = 1.0f - al2;
    const float sh2 = om2 * (bn2_beta[tid] - bn2_mean[tid] * sc2);
    const float scom = sc2 * om2;
    const float rh2 = rho2[tid], ba2 = beta_a2[tid];
    float v2 = 0.f, a2 = 0.f, s2 = 0.f;

    float vo = 0.f, acc = 0.f, bo = 0.f, obo = 0.f;
    if (tid < OO) { bo = beta_out[tid]; obo = 1.0f - bo; }

    __syncthreads();

    for (int t = 0; t < TT; t++) {
        const int q = t & 1, p = q ^ 1;

        float d0 = 0.f, d1 = 0.f;
        #pragma unroll
        for (int c = 0; c < CC; c++) { float xv = xd[t][c]; d0 += Wd0[c] * xv; d1 += Wd1[c] * xv; }
        float r0 = 0.f, r1 = 0.f;
        {
            int n = c1[p];
            for (int j = 0; j < n; j++) {
                int jj = l1[p][j];
                r0 += W_rec1[(size_t)h0 * H1 + jj];
                r1 += W_rec1[(size_t)h1 * H1 + jj];
            }
        }
        {
            float I  = sf0 * (d0 + r0) + shc0;
            float an = rh10 * a10 + ba10 * s10;
            float vn = al10 * v10 + I - an - s10;
            float sn = (vn >= 1.0f) ? 1.0f : 0.0f;
            a10 = an; v10 = vn; s10 = sn;
            if (sn != 0.0f) { int pos = atomicAdd(&c1[q], 1); l1[q][pos] = h0; }
        }
        {
            float I  = sf1 * (d1 + r1) + shc1;
            float an = rh11 * a11 + ba11 * s11;
            float vn = al11 * v11 + I - an - s11;
            float sn = (vn >= 1.0f) ? 1.0f : 0.0f;
            a11 = an; v11 = vn; s11 = sn;
            if (sn != 0.0f) { int pos = atomicAdd(&c1[q], 1); l1[q][pos] = h1; }
        }
        __syncthreads();

        {
            float su = 0.f;
            int m = c1[q];
            for (int j = 0; j < m; j++) su += W2[(size_t)tid * H1 + l1[q][j]];
            int m2 = c2[p];
            for (int j = 0; j < m2; j++) su += W_rec2[(size_t)tid * H2 + l2[p][j]];
            float u  = sh2 + scom * su;
            float an = rh2 * a2 + ba2 * s2;
            float vn = al2 * v2 + u - an - s2;
            float sn = (vn >= 1.0f) ? 1.0f : 0.0f;
            a2 = an; v2 = vn; s2 = sn;
            if (sn != 0.0f) { int pos = atomicAdd(&c2[q], 1); l2[q][pos] = tid; }
        }
        __syncthreads();

        if (tid < OO) {
            float io = 0.f;
            int m = c2[q];
            for (int j = 0; j < m; j++) io += W_out[(size_t)tid * H2 + l2[q][j]];
            vo = bo * vo + obo * io;
            acc += vo;
        }
        if (tid == 0) { c1[p] = 0; c2[p] = 0; }
        __syncthreads();
    }

    if (tid < OO) out[b * OO + tid] = acc * (1.0f / (float)TT);
}

// ---------------- launch ----------------
extern "C" void kernel_launch(void* const* d_in, const int* in_sizes, int n_in,
                              void* d_out, int out_size)
{
    const float* x         = (const float*)d_in[0];
    const float* W_delay   = (const float*)d_in[1];
    const float* delay_raw = (const float*)d_in[2];
    const float* W_rec1    = (const float*)d_in[3];
    const float* W2        = (const float*)d_in[4];
    const float* W_rec2    = (const float*)d_in[5];
    const float* W_out     = (const float*)d_in[6];
    const float* bn1_gamma = (const float*)d_in[7];
    const float* bn1_beta  = (const float*)d_in[8];
    const float* bn1_mean  = (const float*)d_in[9];
    const float* bn1_var   = (const float*)d_in[10];
    const float* bn2_gamma = (const float*)d_in[11];
    const float* bn2_beta  = (const float*)d_in[12];
    const float* bn2_mean  = (const float*)d_in[13];
    const float* bn2_var   = (const float*)d_in[14];
    const float* alpha1    = (const float*)d_in[15];
    const float* rho1      = (const float*)d_in[16];
    const float* beta_a1   = (const float*)d_in[17];
    const float* alpha2    = (const float*)d_in[18];
    const float* rho2      = (const float*)d_in[19];
    const float* beta_a2   = (const float*)d_in[20];
    const float* beta_out  = (const float*)d_in[21];

    static int s_attr_done = 0;
    if (!s_attr_done) {
        cudaFuncSetAttribute(fused_mma_scan_kernel,
                             cudaFuncAttributeMaxDynamicSharedMemorySize, SMEM_BYTES);
        s_attr_done = 1;
    }

    prep_xd_kernel<<<BB * 4 + 8, 256>>>(x, delay_raw, W_delay,
                                        bn1_gamma, bn1_beta, bn1_mean, bn1_var, alpha1);

    fused_mma_scan_kernel<<<BB * 8, 256, SMEM_BYTES>>>(
        alpha1, rho1, beta_a1,
        bn2_gamma, bn2_beta, bn2_mean, bn2_var, alpha2,
        (float*)d_out);

    finalize_kernel<<<BB, 512>>>(x, delay_raw, W_delay,
                                 bn1_gamma, bn1_beta, bn1_mean, bn1_var,
                                 alpha1, rho1, beta_a1,
                                 bn2_gamma, bn2_beta, bn2_mean, bn2_var,
                                 alpha2, rho2, beta_a2,
                                 W_rec1, W2, W_rec2, W_out, beta_out,
                                 (float*)d_out);
}